// round 8
// baseline (speedup 1.0000x reference)
#include <cuda_runtime.h>
#include <math.h>

#define Bsz 4
#define Dd  96
#define Hh  64
#define Ww  64
#define Ll  4096
#define Kk  4
#define Nn  16
#define Rr  6
#define C38 38
#define NCk 64   // number of chunks
#define LCk 64   // chunk length (NCk*LCk == Ll)

// ---------------- scratch (__device__ globals; no allocations) ----------------
__device__ float  g_xpf  [Bsz*Ll*Dd];           // x permuted (B,L,D), row-major spatial
__device__ float  g_xpt  [Bsz*Ll*Dd];           // x permuted (B,L,D), col-major spatial
__device__ float  g_delta[Bsz*Kk*Ll*Dd];        // softplus(delta) (B,K,L,D)
__device__ float  g_dts  [Bsz*Kk*Ll*Rr];        // low-rank dt coefficients
__device__ float  g_Bsc  [Bsz*Kk*Ll*Nn];        // Bs (B,K,L,N)
__device__ float  g_Csc  [Bsz*Kk*Ll*Nn];        // Cs (B,K,L,N)
__device__ float2 g_Phc  [Bsz*Kk*NCk*Dd*Nn];    // interleaved (chunk decay P, end state hc)
__device__ float  g_hin  [Bsz*Kk*NCk*Dd*Nn];    // chunk incoming states
__device__ float  g_ys   [Kk*Bsz*Ll*Dd];        // per-direction y in merge-target space

__device__ __forceinline__ float ex2f(float x){
    float r; asm("ex2.approx.ftz.f32 %0, %1;" : "=f"(r) : "f"(x)); return r;
}
__device__ __forceinline__ float lg2f(float x){
    float r; asm("lg2.approx.ftz.f32 %0, %1;" : "=f"(r) : "f"(x)); return r;
}
__device__ __forceinline__ float softplus_f(float x){
    // max(x,0) + ln2*log2(1 + 2^(-|x|*log2e))
    float e = ex2f(-fabsf(x)*1.4426950408889634f);
    return fmaxf(x, 0.f) + 0.6931471805599453f*lg2f(1.f + e);
}

// ---------------- kernel 1: transpose x -> (B,L,D) in both traversal orders ---
__global__ void k_transpose(const float* __restrict__ x){
    __shared__ float tile[32][33];
    int b = blockIdx.z, d0 = blockIdx.y*32, l0 = blockIdx.x*32;
    int tx = threadIdx.x, ty = threadIdx.y;     // block (32,8)
    #pragma unroll
    for (int i=0;i<4;i++){
        tile[ty+8*i][tx] = x[((long)b*Dd + d0+ty+8*i)*Ll + l0+tx];
    }
    __syncthreads();
    #pragma unroll
    for (int i=0;i<4;i++){
        int l = l0 + ty + 8*i;
        int d = d0 + tx;
        float v = tile[tx][ty+8*i];
        g_xpf[((long)b*Ll + l)*Dd + d] = v;
        int lp = ((l & 63) << 6) | (l >> 6);    // spatial transpose index
        g_xpt[((long)b*Ll + lp)*Dd + d] = v;
    }
}

// ---------------- kernel 2: x_dbl GEMM, register-tiled ------------------------
// Tile: 64 positions x 40 channels (38 padded). 160 threads, each 4x4.
// sx: [d][p] stride 68 (16B-aligned rows), sw: [d][c] stride 44, sy overlays sx.
#define TPp 64
#define TCc 40
__global__ void __launch_bounds__(160) k_projBC(const float* __restrict__ xw){
    __shared__ float pool[Dd*68];      // sx, later sy
    __shared__ float sw[Dd*44];
    int k = blockIdx.y, b = blockIdx.z;
    int p0 = blockIdx.x*TPp;
    int tid = threadIdx.x;
    int cc = tid % 10, pc = tid / 10;  // 4*cc channel base, 4*pc position base

    const float* xp = ((k & 1) ? g_xpt : g_xpf) + ((long)b*Ll + p0)*Dd;
    for (int i=tid; i<TPp*Dd; i+=160){
        int p = i/Dd, d = i - p*Dd;
        pool[d*68 + p] = xp[p*Dd + d];
    }
    const float* wk = xw + k*C38*Dd;
    for (int i=tid; i<TCc*Dd; i+=160){
        int c = i/Dd, d = i - c*Dd;
        sw[d*44 + c] = (c < C38) ? wk[c*Dd + d] : 0.f;
    }
    __syncthreads();

    float acc[4][4];
    #pragma unroll
    for (int i=0;i<4;i++)
        #pragma unroll
        for (int j=0;j<4;j++) acc[i][j] = 0.f;

    #pragma unroll 4
    for (int d=0; d<Dd; d++){
        float4 xv = *reinterpret_cast<const float4*>(pool + d*68 + 4*pc);
        float4 wv = *reinterpret_cast<const float4*>(sw  + d*44 + 4*cc);
        acc[0][0]+=xv.x*wv.x; acc[0][1]+=xv.x*wv.y; acc[0][2]+=xv.x*wv.z; acc[0][3]+=xv.x*wv.w;
        acc[1][0]+=xv.y*wv.x; acc[1][1]+=xv.y*wv.y; acc[1][2]+=xv.y*wv.z; acc[1][3]+=xv.y*wv.w;
        acc[2][0]+=xv.z*wv.x; acc[2][1]+=xv.z*wv.y; acc[2][2]+=xv.z*wv.z; acc[2][3]+=xv.z*wv.w;
        acc[3][0]+=xv.w*wv.x; acc[3][1]+=xv.w*wv.y; acc[3][2]+=xv.w*wv.z; acc[3][3]+=xv.w*wv.w;
    }
    __syncthreads();
    // stage results: sy[p][c], stride 41
    float* sy = pool;
    #pragma unroll
    for (int i=0;i<4;i++)
        #pragma unroll
        for (int j=0;j<4;j++)
            sy[(4*pc+i)*41 + 4*cc+j] = acc[i][j];
    __syncthreads();

    long bk = (long)b*Kk + k;
    // Bs
    for (int i=tid; i<TPp*Nn; i+=160){
        int p = i >> 4, n = i & 15;
        int lo = (k < 2) ? (p0+p) : (Ll-1-(p0+p));
        g_Bsc[(bk*Ll + lo)*Nn + n] = sy[p*41 + Rr + n];
    }
    // Cs
    for (int i=tid; i<TPp*Nn; i+=160){
        int p = i >> 4, n = i & 15;
        int lo = (k < 2) ? (p0+p) : (Ll-1-(p0+p));
        g_Csc[(bk*Ll + lo)*Nn + n] = sy[p*41 + Rr + Nn + n];
    }
    // dts
    for (int i=tid; i<TPp*Rr; i+=160){
        int p = i/Rr, r = i - p*Rr;
        int lo = (k < 2) ? (p0+p) : (Ll-1-(p0+p));
        g_dts[(bk*Ll + lo)*Rr + r] = sy[p*41 + r];
    }
}

// ---------------- kernel 2b: delta = softplus(dts @ dtW^T + bias) -------------
__global__ void __launch_bounds__(384) k_delta(const float* __restrict__ dtw,
                                               const float* __restrict__ dtb){
    __shared__ float sW[Dd*Rr];
    __shared__ float sb[Dd];
    __shared__ float sdts[4][Rr];
    int d = threadIdx.x;              // block (96,4)
    int ty = threadIdx.y;
    long pos0 = (long)blockIdx.x*4;   // 4 consecutive (bk,l) positions, same k
    int k = (int)((pos0 >> 12) & 3);  // pos = bk*Ll + l, Ll=4096, K=4

    for (int t = ty*Dd + d; t < Dd*Rr; t += 384)     // FIX: full coverage of sW
        sW[t] = dtw[k*Dd*Rr + t];
    if (ty == 0) sb[d] = dtb[k*Dd + d];
    if (d < Rr) sdts[ty][d] = g_dts[(pos0+ty)*Rr + d];
    __syncthreads();

    float acc = sb[d];
    #pragma unroll
    for (int r=0;r<Rr;r++) acc += sdts[ty][r]*sW[d*Rr + r];
    g_delta[(pos0+ty)*Dd + d] = softplus_f(acc);
}

// ---------------- kernel 3: pass A (chunk-local scan, zero init) --------------
__global__ void __launch_bounds__(Dd) k_scanA(const float* __restrict__ A_logs){
    __shared__ float4 sB[LCk*Nn/4];
    int c = blockIdx.x, k = blockIdx.y, b = blockIdx.z;
    int d = threadIdx.x;
    long bk = (long)b*Kk + k;

    const float4* gB4 = reinterpret_cast<const float4*>(g_Bsc + (bk*Ll + (long)c*LCk)*Nn);
    for (int i=d; i<LCk*Nn/4; i+=Dd) sB[i] = gB4[i];
    __syncthreads();

    float A2[Nn];
    const float* al = A_logs + (k*Dd + d)*Nn;
    #pragma unroll
    for (int n=0;n<Nn;n++) A2[n] = -__expf(al[n]) * 1.4426950408889634f;

    float h[Nn];
    #pragma unroll
    for (int n=0;n<Nn;n++) h[n] = 0.f;
    float S = 0.f;

    const float* dptr = g_delta + (bk*Ll + (long)c*LCk)*Dd + d;
    const float* xp = (k & 1) ? g_xpt : g_xpf;
    int l0 = c*LCk;
    const float* uptr; int ustr;
    if (k < 2){ uptr = xp + ((long)b*Ll + l0)*Dd + d;           ustr =  Dd; }
    else      { uptr = xp + ((long)b*Ll + (Ll-1-l0))*Dd + d;    ustr = -Dd; }

    #pragma unroll 2
    for (int j=0;j<LCk;j++){
        float dlt = dptr[j*Dd];
        float u = *uptr; uptr += ustr;
        float du = dlt*u;
        S += dlt;
        const float4* bj = sB + j*(Nn/4);
        #pragma unroll
        for (int q=0;q<Nn/4;q++){
            float4 bb = bj[q];
            h[4*q+0] = h[4*q+0]*ex2f(dlt*A2[4*q+0]) + du*bb.x;
            h[4*q+1] = h[4*q+1]*ex2f(dlt*A2[4*q+1]) + du*bb.y;
            h[4*q+2] = h[4*q+2]*ex2f(dlt*A2[4*q+2]) + du*bb.z;
            h[4*q+3] = h[4*q+3]*ex2f(dlt*A2[4*q+3]) + du*bb.w;
        }
    }
    long base = ((bk*NCk + c)*Dd + d)*Nn;   // in float2 units
    float4* pp = reinterpret_cast<float4*>(g_Phc + base);
    #pragma unroll
    for (int q=0;q<Nn/2;q++){
        pp[q] = make_float4(ex2f(A2[2*q]*S),   h[2*q],
                            ex2f(A2[2*q+1]*S), h[2*q+1]);
    }
}

// ---------------- kernel 4: inter-chunk scan (software-pipelined loads) ------
#define MID_G 16
#define MID_NG (NCk/MID_G)
__global__ void __launch_bounds__(256) k_mid(){
    int g = blockIdx.x*blockDim.x + threadIdx.x;   // B*K*D*N threads
    if (g >= Bsz*Kk*Dd*Nn) return;
    const int STR = Dd*Nn;                         // stride between chunks
    long base0 = g + ((long)(g / (Dd*Nn))) * (long)(NCk-1) * STR;

    float2 PH[2][MID_G];

    #pragma unroll
    for (int i=0;i<MID_G;i++)
        PH[0][i] = g_Phc[base0 + (long)i*STR];

    float hin = 0.f;
    #pragma unroll
    for (int grp=0; grp<MID_NG; grp++){
        int cur = grp & 1, nxt = cur ^ 1;
        if (grp+1 < MID_NG){
            #pragma unroll
            for (int i=0;i<MID_G;i++)
                PH[nxt][i] = g_Phc[base0 + (long)((grp+1)*MID_G + i)*STR];
        }
        #pragma unroll
        for (int i=0;i<MID_G;i++){
            long idx = base0 + (long)(grp*MID_G + i)*STR;
            g_hin[idx] = hin;
            hin = hin*PH[cur][i].x + PH[cur][i].y;
        }
    }
}

// ---------------- kernel 5: pass B (replay with correct h_in, emit y) --------
__global__ void __launch_bounds__(Dd) k_scanB(const float* __restrict__ A_logs,
                                              const float* __restrict__ Ds){
    __shared__ float4 sB[LCk*Nn/4];
    __shared__ float4 sC[LCk*Nn/4];
    int c = blockIdx.x, k = blockIdx.y, b = blockIdx.z;
    int d = threadIdx.x;
    long bk = (long)b*Kk + k;

    const float4* gB4 = reinterpret_cast<const float4*>(g_Bsc + (bk*Ll + (long)c*LCk)*Nn);
    const float4* gC4 = reinterpret_cast<const float4*>(g_Csc + (bk*Ll + (long)c*LCk)*Nn);
    for (int i=d; i<LCk*Nn/4; i+=Dd){ sB[i] = gB4[i]; sC[i] = gC4[i]; }
    __syncthreads();

    float A2[Nn];
    const float* al = A_logs + (k*Dd + d)*Nn;
    #pragma unroll
    for (int n=0;n<Nn;n++) A2[n] = -__expf(al[n]) * 1.4426950408889634f;

    float h[Nn];
    long base = ((bk*NCk + c)*Dd + d)*Nn;
    #pragma unroll
    for (int q=0;q<Nn/4;q++){
        float4 v = reinterpret_cast<const float4*>(g_hin + base)[q];
        h[4*q]=v.x; h[4*q+1]=v.y; h[4*q+2]=v.z; h[4*q+3]=v.w;
    }
    float Dskip = Ds[k*Dd + d];

    const float* dptr = g_delta + (bk*Ll + (long)c*LCk)*Dd + d;
    const float* xp = (k & 1) ? g_xpt : g_xpf;
    int l0 = c*LCk;
    const float* uptr; int ustr;
    if (k < 2){ uptr = xp + ((long)b*Ll + l0)*Dd + d;        ustr =  Dd; }
    else      { uptr = xp + ((long)b*Ll + (Ll-1-l0))*Dd + d; ustr = -Dd; }

    float* yout = g_ys + ((long)k*Bsz + b)*Ll*Dd + d;

    #pragma unroll 2
    for (int j=0;j<LCk;j++){
        float dlt = dptr[j*Dd];
        float u = *uptr; uptr += ustr;
        float du = dlt*u;
        float y = Dskip*u;
        const float4* bj = sB + j*(Nn/4);
        const float4* cj = sC + j*(Nn/4);
        #pragma unroll
        for (int q=0;q<Nn/4;q++){
            float4 bb = bj[q];
            float4 cc = cj[q];
            h[4*q+0] = h[4*q+0]*ex2f(dlt*A2[4*q+0]) + du*bb.x;  y += h[4*q+0]*cc.x;
            h[4*q+1] = h[4*q+1]*ex2f(dlt*A2[4*q+1]) + du*bb.y;  y += h[4*q+1]*cc.y;
            h[4*q+2] = h[4*q+2]*ex2f(dlt*A2[4*q+2]) + du*bb.z;  y += h[4*q+2]*cc.z;
            h[4*q+3] = h[4*q+3]*ex2f(dlt*A2[4*q+3]) + du*bb.w;  y += h[4*q+3]*cc.w;
        }
        int l = l0 + j;
        int t;
        if (k == 0)      t = l;
        else if (k == 1) t = ((l & 63) << 6) | (l >> 6);
        else if (k == 2) t = Ll-1-l;
        else { int q2 = Ll-1-l; t = ((q2 & 63) << 6) | (q2 >> 6); }
        yout[(long)t*Dd] = y;
    }
}

// ---------------- kernel 6: 4-way merge + LayerNorm --------------------------
__global__ void __launch_bounds__(256) k_merge(const float* __restrict__ lnw,
                                               const float* __restrict__ lnb,
                                               float* __restrict__ out){
    const long BLD = (long)Bsz*Ll*Dd;
    int warp = threadIdx.x >> 5, lane = threadIdx.x & 31;
    int pos = blockIdx.x*8 + warp;
    int b = pos >> 12;              // Ll = 4096
    int l = pos & (Ll-1);
    long base = ((long)b*Ll + l)*Dd;
    float s[3]; float sum = 0.f, sq = 0.f;
    #pragma unroll
    for (int i=0;i<3;i++){
        long off = base + lane + 32*i;
        float v = g_ys[off] + g_ys[off + BLD] + g_ys[off + 2*BLD] + g_ys[off + 3*BLD];
        s[i] = v; sum += v; sq += v*v;
    }
    #pragma unroll
    for (int o2=16;o2>0;o2>>=1){
        sum += __shfl_xor_sync(0xffffffffu, sum, o2);
        sq  += __shfl_xor_sync(0xffffffffu, sq,  o2);
    }
    float mean = sum * (1.f/Dd);
    float var  = sq  * (1.f/Dd) - mean*mean;
    float inv  = rsqrtf(var + 1e-5f);
    #pragma unroll
    for (int i=0;i<3;i++){
        int dch = lane + 32*i;
        out[base + dch] = (s[i]-mean)*inv*lnw[dch] + lnb[dch];
    }
}

// ---------------- launch ------------------------------------------------------
extern "C" void kernel_launch(void* const* d_in, const int* in_sizes, int n_in,
                              void* d_out, int out_size){
    const float* x     = (const float*)d_in[0];
    const float* xw    = (const float*)d_in[1];
    const float* dtw   = (const float*)d_in[2];
    const float* dtb   = (const float*)d_in[3];
    const float* alogs = (const float*)d_in[4];
    const float* Ds    = (const float*)d_in[5];
    const float* lnw   = (const float*)d_in[6];
    const float* lnb   = (const float*)d_in[7];
    float* out = (float*)d_out;

    k_transpose<<<dim3(Ll/32, Dd/32, Bsz), dim3(32,8)>>>(x);
    k_projBC   <<<dim3(Ll/TPp, Kk, Bsz), 160>>>(xw);
    k_delta    <<<Bsz*Kk*Ll/4, dim3(Dd,4)>>>(dtw, dtb);
    k_scanA    <<<dim3(NCk, Kk, Bsz), Dd>>>(alogs);
    k_mid      <<<(Bsz*Kk*Dd*Nn + 255)/256, 256>>>();
    k_scanB    <<<dim3(NCk, Kk, Bsz), Dd>>>(alogs, Ds);
    k_merge    <<<Bsz*Ll/8, 256>>>(lnw, lnb, out);
}